// round 2
// baseline (speedup 1.0000x reference)
#include <cuda_runtime.h>
#include <math.h>

#define B_   8
#define W_   1024
#define H_   16
#define D_   64
#define BH_  (B_ * H_)
#define NQKV (B_ * W_ * H_ * D_)        /* 8,388,608  */
#define NATT ((size_t)BH_ * W_ * W_)    /* 134,217,728 */

#define FLT_BIG 3.402823466e38f

// persistent scratch (static __device__ allocations are allowed)
__device__ float g_qf[NQKV];
__device__ float g_kf[NQKV];
__device__ float g_vf[NQKV];
// min/max accumulators (ordered-uint encoding), slots:
// 0=q 1=k 2=v 3=scores 4=att 5=ctx
__device__ unsigned g_omin[6];
__device__ unsigned g_omax[6];

// ---------------- float <-> order-preserving uint ----------------
__device__ __forceinline__ unsigned f2o(float f) {
    unsigned u = __float_as_uint(f);
    return (u & 0x80000000u) ? ~u : (u | 0x80000000u);
}
__device__ __forceinline__ float o2f(unsigned u) {
    return (u & 0x80000000u) ? __uint_as_float(u & 0x7fffffffu)
                             : __uint_as_float(~u);
}

// ---------------- fake-quant (matches jnp reference) ----------------
__device__ __forceinline__ float fq_apply(float x, int slot) {
    float mn = o2f(g_omin[slot]);
    float mx = o2f(g_omax[slot]);
    float scale = fmaxf((mx - mn) / 255.0f, 1e-8f);
    float zp = fminf(fmaxf(rintf(-128.0f - mn / scale), -128.0f), 127.0f);
    float q  = fminf(fmaxf(rintf(x / scale) + zp, -128.0f), 127.0f);
    return (q - zp) * scale;
}

// ---------------- block min/max -> global atomics ----------------
// tid MUST be the linear thread index within the block; nthreads the block size.
__device__ __forceinline__ void block_minmax_commit(float vmin, float vmax, int slot,
                                                    int tid, int nthreads) {
    #pragma unroll
    for (int o = 16; o; o >>= 1) {
        vmin = fminf(vmin, __shfl_xor_sync(0xffffffffu, vmin, o));
        vmax = fmaxf(vmax, __shfl_xor_sync(0xffffffffu, vmax, o));
    }
    __shared__ float smn[8], smx[8];
    int w = tid >> 5, l = tid & 31;
    int nw = (nthreads + 31) >> 5;
    if (l == 0) { smn[w] = vmin; smx[w] = vmax; }
    __syncthreads();
    if (w == 0) {
        vmin = (l < nw) ? smn[l] : FLT_BIG;
        vmax = (l < nw) ? smx[l] : -FLT_BIG;
        #pragma unroll
        for (int o = 4; o; o >>= 1) {
            vmin = fminf(vmin, __shfl_xor_sync(0xffffffffu, vmin, o));
            vmax = fmaxf(vmax, __shfl_xor_sync(0xffffffffu, vmax, o));
        }
        if (l == 0) {
            atomicMin(&g_omin[slot], f2o(vmin));
            atomicMax(&g_omax[slot], f2o(vmax));
        }
    }
    __syncthreads();
}

// ---------------- kernels ----------------
__global__ void k_init() {
    int i = threadIdx.x;
    if (i < 6) { g_omin[i] = 0xFFFFFFFFu; g_omax[i] = 0u; }
}

__global__ void __launch_bounds__(256) k_minmax(const float* __restrict__ x, int n, int slot) {
    float vmin = FLT_BIG, vmax = -FLT_BIG;
    for (int i = blockIdx.x * blockDim.x + threadIdx.x; i < n; i += gridDim.x * blockDim.x) {
        float v = x[i];
        vmin = fminf(vmin, v);
        vmax = fmaxf(vmax, v);
    }
    block_minmax_commit(vmin, vmax, slot, threadIdx.x, 256);
}

__global__ void __launch_bounds__(256) k_fq3(const float* __restrict__ q,
                                             const float* __restrict__ k,
                                             const float* __restrict__ v) {
    for (int i = blockIdx.x * blockDim.x + threadIdx.x; i < NQKV; i += gridDim.x * blockDim.x) {
        g_qf[i] = fq_apply(q[i], 0);
        g_kf[i] = fq_apply(k[i], 1);
        g_vf[i] = fq_apply(v[i], 2);
    }
}

// scores[bh, qi, ki] = (1/8) * sum_d qf[b,qi,h,d] * kf[b,ki,h,d]
// grid (16,16,128), block (16,16). Also reduces scores min/max (slot 3).
__global__ void __launch_bounds__(256) k_scores(float* __restrict__ scores) {
    __shared__ float As[64][65];
    __shared__ float Bs[64][65];

    int bh = blockIdx.z;
    int b = bh >> 4, h = bh & 15;
    int q0 = blockIdx.y * 64, k0 = blockIdx.x * 64;
    int tx = threadIdx.x, ty = threadIdx.y;
    int tid = ty * 16 + tx;

    const float* Aq = g_qf + ((size_t)(b * W_ + q0) * H_ + h) * D_;
    const float* Bk = g_kf + ((size_t)(b * W_ + k0) * H_ + h) * D_;

    // 64 rows x 64 floats per tile: 1024 float4 slots / 256 threads = 4 each
    #pragma unroll
    for (int t = tid; t < 1024; t += 256) {
        int r = t >> 4, c = (t & 15) * 4;
        float4 va = *(const float4*)(Aq + (size_t)r * (H_ * D_) + c);
        As[r][c] = va.x; As[r][c+1] = va.y; As[r][c+2] = va.z; As[r][c+3] = va.w;
        float4 vb = *(const float4*)(Bk + (size_t)r * (H_ * D_) + c);
        Bs[r][c] = vb.x; Bs[r][c+1] = vb.y; Bs[r][c+2] = vb.z; Bs[r][c+3] = vb.w;
    }
    __syncthreads();

    float acc[4][4] = {};
    #pragma unroll 16
    for (int d = 0; d < 64; d++) {
        float a[4], bb[4];
        #pragma unroll
        for (int i = 0; i < 4; i++) a[i] = As[ty * 4 + i][d];
        #pragma unroll
        for (int j = 0; j < 4; j++) bb[j] = Bs[tx * 4 + j][d];
        #pragma unroll
        for (int i = 0; i < 4; i++)
            #pragma unroll
            for (int j = 0; j < 4; j++)
                acc[i][j] += a[i] * bb[j];
    }

    float vmin = FLT_BIG, vmax = -FLT_BIG;
    #pragma unroll
    for (int i = 0; i < 4; i++) {
        float4 o;
        float* pv = &o.x;
        #pragma unroll
        for (int j = 0; j < 4; j++) {
            float v = acc[i][j] * 0.125f;
            pv[j] = v;
            vmin = fminf(vmin, v);
            vmax = fmaxf(vmax, v);
        }
        size_t off = ((size_t)bh * W_ + q0 + ty * 4 + i) * W_ + k0 + tx * 4;
        *(float4*)(scores + off) = o;
    }
    block_minmax_commit(vmin, vmax, 3, tid, 256);
}

// per-row: fq(scores, slot3) -> softmax -> write att (pre-fq) -> minmax slot4
__global__ void __launch_bounds__(256) k_softmax(float* __restrict__ att) {
    size_t row = blockIdx.x;
    float* p = att + row * W_;
    int t = threadIdx.x;

    float4 v = ((float4*)p)[t];
    v.x = fq_apply(v.x, 3); v.y = fq_apply(v.y, 3);
    v.z = fq_apply(v.z, 3); v.w = fq_apply(v.w, 3);

    __shared__ float sredA[8];
    __shared__ float sredB[8];
    int w = t >> 5, l = t & 31;

    // row max
    float m = fmaxf(fmaxf(v.x, v.y), fmaxf(v.z, v.w));
    #pragma unroll
    for (int o = 16; o; o >>= 1) m = fmaxf(m, __shfl_xor_sync(0xffffffffu, m, o));
    if (l == 0) sredA[w] = m;
    __syncthreads();
    m = sredA[0];
    #pragma unroll
    for (int i = 1; i < 8; i++) m = fmaxf(m, sredA[i]);

    float4 e;
    e.x = expf(v.x - m); e.y = expf(v.y - m);
    e.z = expf(v.z - m); e.w = expf(v.w - m);

    // row sum
    float s = e.x + e.y + e.z + e.w;
    #pragma unroll
    for (int o = 16; o; o >>= 1) s += __shfl_xor_sync(0xffffffffu, s, o);
    if (l == 0) sredB[w] = s;
    __syncthreads();
    s = sredB[0];
    #pragma unroll
    for (int i = 1; i < 8; i++) s += sredB[i];

    e.x = e.x / s; e.y = e.y / s; e.z = e.z / s; e.w = e.w / s;
    ((float4*)p)[t] = e;

    float vmin = fminf(fminf(e.x, e.y), fminf(e.z, e.w));
    float vmax = fmaxf(fmaxf(e.x, e.y), fmaxf(e.z, e.w));
    block_minmax_commit(vmin, vmax, 4, t, 256);
}

// ctx[b,qi,h,d] = sum_k fq(att[bh,qi,k],4) * vf[b,k,h,d]
// Also writes quantized att back in place, and reduces ctx min/max (slot 5).
// grid (16,128), block (16,16).
__global__ void __launch_bounds__(256) k_attgemm(float* __restrict__ att,
                                                 float* __restrict__ ctx) {
    __shared__ float As[64][65];
    __shared__ float Bs[64][65];

    int bh = blockIdx.y;
    int b = bh >> 4, h = bh & 15;
    int q0 = blockIdx.x * 64;
    int tx = threadIdx.x, ty = threadIdx.y;
    int tid = ty * 16 + tx;

    float acc[4][4] = {};

    for (int kk = 0; kk < W_; kk += 64) {
        // att tile: fq on load, write quantized att back
        #pragma unroll
        for (int t = tid; t < 1024; t += 256) {
            int r = t >> 4, c = (t & 15) * 4;
            float* ap = att + ((size_t)bh * W_ + q0 + r) * W_ + kk + c;
            float4 va = *(float4*)ap;
            va.x = fq_apply(va.x, 4); va.y = fq_apply(va.y, 4);
            va.z = fq_apply(va.z, 4); va.w = fq_apply(va.w, 4);
            *(float4*)ap = va;
            As[r][c] = va.x; As[r][c+1] = va.y; As[r][c+2] = va.z; As[r][c+3] = va.w;
        }
        // vf tile: Bs[kr][d]
        const float* Bv = g_vf + ((size_t)(b * W_ + kk) * H_ + h) * D_;
        #pragma unroll
        for (int t = tid; t < 1024; t += 256) {
            int r = t >> 4, c = (t & 15) * 4;
            float4 vb = *(const float4*)(Bv + (size_t)r * (H_ * D_) + c);
            Bs[r][c] = vb.x; Bs[r][c+1] = vb.y; Bs[r][c+2] = vb.z; Bs[r][c+3] = vb.w;
        }
        __syncthreads();

        #pragma unroll 16
        for (int k = 0; k < 64; k++) {
            float a[4], bb[4];
            #pragma unroll
            for (int i = 0; i < 4; i++) a[i] = As[ty * 4 + i][k];
            #pragma unroll
            for (int j = 0; j < 4; j++) bb[j] = Bs[k][tx * 4 + j];
            #pragma unroll
            for (int i = 0; i < 4; i++)
                #pragma unroll
                for (int j = 0; j < 4; j++)
                    acc[i][j] += a[i] * bb[j];
        }
        __syncthreads();
    }

    float vmin = FLT_BIG, vmax = -FLT_BIG;
    #pragma unroll
    for (int i = 0; i < 4; i++) {
        float4 o;
        float* pv = &o.x;
        #pragma unroll
        for (int j = 0; j < 4; j++) {
            float v = acc[i][j];
            pv[j] = v;
            vmin = fminf(vmin, v);
            vmax = fmaxf(vmax, v);
        }
        size_t off = ((size_t)(b * W_ + q0 + ty * 4 + i) * H_ + h) * D_ + tx * 4;
        *(float4*)(ctx + off) = o;
    }
    block_minmax_commit(vmin, vmax, 5, tid, 256);
}

__global__ void __launch_bounds__(256) k_fqctx(float* __restrict__ ctx) {
    for (int i = blockIdx.x * blockDim.x + threadIdx.x; i < NQKV; i += gridDim.x * blockDim.x) {
        ctx[i] = fq_apply(ctx[i], 5);
    }
}

// ---------------- launch ----------------
extern "C" void kernel_launch(void* const* d_in, const int* in_sizes, int n_in,
                              void* d_out, int out_size) {
    const float* q = (const float*)d_in[0];
    const float* k = (const float*)d_in[1];
    const float* v = (const float*)d_in[2];

    float* ctx = (float*)d_out;
    // att is the trailing NATT elements of the output (context first, att second)
    float* att = (float*)d_out + ((size_t)out_size - NATT);

    k_init<<<1, 32>>>();

    k_minmax<<<1024, 256>>>(q, NQKV, 0);
    k_minmax<<<1024, 256>>>(k, NQKV, 1);
    k_minmax<<<1024, 256>>>(v, NQKV, 2);

    k_fq3<<<2048, 256>>>(q, k, v);

    dim3 blk(16, 16);
    dim3 gsc(16, 16, BH_);
    k_scores<<<gsc, blk>>>(att);

    k_softmax<<<BH_ * W_, 256>>>(att);

    dim3 gag(16, BH_);
    k_attgemm<<<gag, blk>>>(att, ctx);

    k_fqctx<<<2048, 256>>>(ctx);
}

// round 4
// speedup vs baseline: 1.9348x; 1.9348x over previous
#include <cuda_runtime.h>
#include <cuda_fp16.h>
#include <stdint.h>
#include <math.h>

#define B_   8
#define W_   1024
#define H_   16
#define D_   64
#define BH_  (B_ * H_)
#define NQKV (B_ * W_ * H_ * D_)        /* 8,388,608  */
#define NATT ((size_t)BH_ * W_ * W_)    /* 134,217,728 */

#define FLT_BIG 3.402823466e38f

// quantized (q_int - zp) values as fp16, layout [BH][W][D]
__device__ __half g_qh[NQKV];
__device__ __half g_kh[NQKV];
__device__ __half g_vh[NQKV];
// min/max accumulators (ordered-uint), slots: 0=q 1=k 2=v 3=scores 4=att 5=ctx
__device__ unsigned g_omin[6];
__device__ unsigned g_omax[6];

// ---------------- float <-> order-preserving uint ----------------
__device__ __forceinline__ unsigned f2o(float f) {
    unsigned u = __float_as_uint(f);
    return (u & 0x80000000u) ? ~u : (u | 0x80000000u);
}
__device__ __forceinline__ float o2f(unsigned u) {
    return (u & 0x80000000u) ? __uint_as_float(u & 0x7fffffffu)
                             : __uint_as_float(~u);
}

// ---------------- fake-quant helpers ----------------
__device__ __forceinline__ void get_sz(int slot, float& s, float& zp) {
    float mn = o2f(g_omin[slot]);
    float mx = o2f(g_omax[slot]);
    s  = fmaxf((mx - mn) / 255.0f, 1e-8f);
    zp = fminf(fmaxf(rintf(-128.0f - mn / s), -128.0f), 127.0f);
}
// returns (q_int - zp): integer-valued float in [-255,255]. dequant = ret * s
__device__ __forceinline__ float fq_q(float x, float s, float zp) {
    return fminf(fmaxf(rintf(x / s) + zp, -128.0f), 127.0f) - zp;
}

// ---------------- block min/max -> global atomics ----------------
__device__ __forceinline__ void block_minmax_commit(float vmin, float vmax, int slot,
                                                    int tid, int nthreads) {
    #pragma unroll
    for (int o = 16; o; o >>= 1) {
        vmin = fminf(vmin, __shfl_xor_sync(0xffffffffu, vmin, o));
        vmax = fmaxf(vmax, __shfl_xor_sync(0xffffffffu, vmax, o));
    }
    __shared__ float smn[8], smx[8];
    int w = tid >> 5, l = tid & 31;
    int nw = (nthreads + 31) >> 5;
    if (l == 0) { smn[w] = vmin; smx[w] = vmax; }
    __syncthreads();
    if (w == 0) {
        vmin = (l < nw) ? smn[l] : FLT_BIG;
        vmax = (l < nw) ? smx[l] : -FLT_BIG;
        #pragma unroll
        for (int o = 4; o; o >>= 1) {
            vmin = fminf(vmin, __shfl_xor_sync(0xffffffffu, vmin, o));
            vmax = fmaxf(vmax, __shfl_xor_sync(0xffffffffu, vmax, o));
        }
        if (l == 0) {
            atomicMin(&g_omin[slot], f2o(vmin));
            atomicMax(&g_omax[slot], f2o(vmax));
        }
    }
    __syncthreads();
}

// ---------------- ldmatrix / mma wrappers ----------------
__device__ __forceinline__ unsigned smem_u32(const void* p) {
    return (unsigned)__cvta_generic_to_shared(p);
}
__device__ __forceinline__ void ldsm_x4(unsigned a, unsigned& r0, unsigned& r1,
                                        unsigned& r2, unsigned& r3) {
    asm volatile("ldmatrix.sync.aligned.m8n8.x4.shared.b16 {%0,%1,%2,%3}, [%4];"
                 : "=r"(r0), "=r"(r1), "=r"(r2), "=r"(r3) : "r"(a));
}
__device__ __forceinline__ void ldsm_x2(unsigned a, unsigned& r0, unsigned& r1) {
    asm volatile("ldmatrix.sync.aligned.m8n8.x2.shared.b16 {%0,%1}, [%2];"
                 : "=r"(r0), "=r"(r1) : "r"(a));
}
__device__ __forceinline__ void ldsm_x2t(unsigned a, unsigned& r0, unsigned& r1) {
    asm volatile("ldmatrix.sync.aligned.m8n8.x2.trans.shared.b16 {%0,%1}, [%2];"
                 : "=r"(r0), "=r"(r1) : "r"(a));
}
__device__ __forceinline__ void mma16816(float* d, unsigned a0, unsigned a1,
                                         unsigned a2, unsigned a3,
                                         unsigned b0, unsigned b1) {
    asm volatile(
        "mma.sync.aligned.m16n8k16.row.col.f32.f16.f16.f32 "
        "{%0,%1,%2,%3}, {%4,%5,%6,%7}, {%8,%9}, {%0,%1,%2,%3};"
        : "+f"(d[0]), "+f"(d[1]), "+f"(d[2]), "+f"(d[3])
        : "r"(a0), "r"(a1), "r"(a2), "r"(a3), "r"(b0), "r"(b1));
}

// ---------------- kernels ----------------
__global__ void k_init() {
    int i = threadIdx.x;
    if (i < 6) { g_omin[i] = 0xFFFFFFFFu; g_omax[i] = 0u; }
}

__global__ void __launch_bounds__(256) k_minmax(const float4* __restrict__ x, int n4, int slot) {
    float vmin = FLT_BIG, vmax = -FLT_BIG;
    for (int i = blockIdx.x * blockDim.x + threadIdx.x; i < n4; i += gridDim.x * blockDim.x) {
        float4 v = x[i];
        vmin = fminf(vmin, fminf(fminf(v.x, v.y), fminf(v.z, v.w)));
        vmax = fmaxf(vmax, fmaxf(fmaxf(v.x, v.y), fmaxf(v.z, v.w)));
    }
    block_minmax_commit(vmin, vmax, slot, threadIdx.x, 256);
}

// quantize q/k/v into fp16 (q_int - zp) values, transposed to [BH][W][D].
// grid = B*W blocks, 256 threads: thread t handles h = t/16, d = (t%16)*4.
__global__ void __launch_bounds__(256) k_quant(const float* __restrict__ q,
                                               const float* __restrict__ k,
                                               const float* __restrict__ v) {
    float s0, z0, s1, z1, s2, z2;
    get_sz(0, s0, z0); get_sz(1, s1, z1); get_sz(2, s2, z2);

    int bw = blockIdx.x;               // b*W + w
    int b = bw >> 10, w = bw & 1023;
    int t = threadIdx.x;
    int h = t >> 4, d4 = (t & 15) * 4;

    size_t src = ((size_t)bw * H_ + h) * D_ + d4;
    size_t dst = (((size_t)(b * H_ + h)) * W_ + w) * D_ + d4;

    union { __half2 h2; unsigned u; } p0, p1;

    float4 fq_v = *(const float4*)(q + src);
    p0.h2 = __floats2half2_rn(fq_q(fq_v.x, s0, z0), fq_q(fq_v.y, s0, z0));
    p1.h2 = __floats2half2_rn(fq_q(fq_v.z, s0, z0), fq_q(fq_v.w, s0, z0));
    *(uint2*)(g_qh + dst) = make_uint2(p0.u, p1.u);

    fq_v = *(const float4*)(k + src);
    p0.h2 = __floats2half2_rn(fq_q(fq_v.x, s1, z1), fq_q(fq_v.y, s1, z1));
    p1.h2 = __floats2half2_rn(fq_q(fq_v.z, s1, z1), fq_q(fq_v.w, s1, z1));
    *(uint2*)(g_kh + dst) = make_uint2(p0.u, p1.u);

    fq_v = *(const float4*)(v + src);
    p0.h2 = __floats2half2_rn(fq_q(fq_v.x, s2, z2), fq_q(fq_v.y, s2, z2));
    p1.h2 = __floats2half2_rn(fq_q(fq_v.z, s2, z2), fq_q(fq_v.w, s2, z2));
    *(uint2*)(g_vh + dst) = make_uint2(p0.u, p1.u);
}

// scores[bh,qi,ki] = (sum_d qh*kh) * s_q*s_k/8.  CTA = 128x128 tile, K=64.
// grid (8, 8, 128), block 256 (8 warps as 2x4). Tensor cores (HMMA).
__global__ void __launch_bounds__(256) k_scores(float* __restrict__ scores) {
    __shared__ uint4 At[128 * 8];      // 128 rows x 64 halves, swizzled 16B chunks
    __shared__ uint4 Kt[128 * 8];

    int bh = blockIdx.z;
    int q0 = blockIdx.y * 128, k0 = blockIdx.x * 128;
    int tid = threadIdx.x;

    const uint4* qsrc = (const uint4*)(g_qh + ((size_t)bh * W_ + q0) * D_);
    const uint4* ksrc = (const uint4*)(g_kh + ((size_t)bh * W_ + k0) * D_);
    #pragma unroll
    for (int i = 0; i < 4; i++) {
        int g = tid + i * 256;
        int r = g >> 3, c = g & 7;
        At[r * 8 + (c ^ (r & 7))] = qsrc[g];
        Kt[r * 8 + (c ^ (r & 7))] = ksrc[g];
    }
    __syncthreads();

    int wid = tid >> 5, l = tid & 31;
    int wm = wid >> 2, wn = wid & 3;   // warp tile: 64 rows x 32 cols

    float acc[4][4][4];
    #pragma unroll
    for (int i = 0; i < 4; i++)
        #pragma unroll
        for (int j = 0; j < 4; j++)
            #pragma unroll
            for (int e = 0; e < 4; e++) acc[i][j][e] = 0.0f;

    unsigned abase = smem_u32(At), kbase = smem_u32(Kt);

    #pragma unroll
    for (int kc = 0; kc < 4; kc++) {
        unsigned a[4][4];
        #pragma unroll
        for (int mi = 0; mi < 4; mi++) {
            int row = wm * 64 + mi * 16 + (l & 15);
            int ch  = kc * 2 + (l >> 4);
            ldsm_x4(abase + (row * 8 + (ch ^ (row & 7))) * 16,
                    a[mi][0], a[mi][1], a[mi][2], a[mi][3]);
        }
        unsigned bf[4][2];
        #pragma unroll
        for (int ni = 0; ni < 4; ni++) {
            int row = wn * 32 + ni * 8 + (l & 7);
            int ch  = kc * 2 + ((l >> 3) & 1);
            ldsm_x2(kbase + (row * 8 + (ch ^ (row & 7))) * 16, bf[ni][0], bf[ni][1]);
        }
        #pragma unroll
        for (int mi = 0; mi < 4; mi++)
            #pragma unroll
            for (int ni = 0; ni < 4; ni++)
                mma16816(acc[mi][ni], a[mi][0], a[mi][1], a[mi][2], a[mi][3],
                         bf[ni][0], bf[ni][1]);
    }

    float s0, z0, s1, z1;
    get_sz(0, s0, z0); get_sz(1, s1, z1);
    float sc = s0 * s1 * 0.125f;

    float vmin = FLT_BIG, vmax = -FLT_BIG;
    #pragma unroll
    for (int mi = 0; mi < 4; mi++) {
        int r0 = q0 + wm * 64 + mi * 16 + (l >> 2);
        #pragma unroll
        for (int ni = 0; ni < 4; ni++) {
            int c = k0 + wn * 32 + ni * 8 + (l & 3) * 2;
            float v0 = acc[mi][ni][0] * sc, v1 = acc[mi][ni][1] * sc;
            float v2 = acc[mi][ni][2] * sc, v3 = acc[mi][ni][3] * sc;
            vmin = fminf(vmin, fminf(fminf(v0, v1), fminf(v2, v3)));
            vmax = fmaxf(vmax, fmaxf(fmaxf(v0, v1), fmaxf(v2, v3)));
            size_t base = ((size_t)bh * W_ + r0) * W_ + c;
            *(float2*)(scores + base)           = make_float2(v0, v1);
            *(float2*)(scores + base + 8 * W_)  = make_float2(v2, v3);
        }
    }
    block_minmax_commit(vmin, vmax, 3, tid, 256);
}

// per-row: fq(scores,3) -> softmax -> write att (pre-fq) -> minmax slot4
__global__ void __launch_bounds__(256) k_softmax(float* __restrict__ att) {
    size_t row = blockIdx.x;
    float* p = att + row * W_;
    int t = threadIdx.x;

    float s3, z3;
    get_sz(3, s3, z3);

    float4 v = ((float4*)p)[t];
    v.x = fq_q(v.x, s3, z3) * s3; v.y = fq_q(v.y, s3, z3) * s3;
    v.z = fq_q(v.z, s3, z3) * s3; v.w = fq_q(v.w, s3, z3) * s3;

    __shared__ float sredA[8];
    __shared__ float sredB[8];
    int w = t >> 5, l = t & 31;

    float m = fmaxf(fmaxf(v.x, v.y), fmaxf(v.z, v.w));
    #pragma unroll
    for (int o = 16; o; o >>= 1) m = fmaxf(m, __shfl_xor_sync(0xffffffffu, m, o));
    if (l == 0) sredA[w] = m;
    __syncthreads();
    m = sredA[0];
    #pragma unroll
    for (int i = 1; i < 8; i++) m = fmaxf(m, sredA[i]);

    float4 e;
    e.x = expf(v.x - m); e.y = expf(v.y - m);
    e.z = expf(v.z - m); e.w = expf(v.w - m);

    float s = e.x + e.y + e.z + e.w;
    #pragma unroll
    for (int o = 16; o; o >>= 1) s += __shfl_xor_sync(0xffffffffu, s, o);
    if (l == 0) sredB[w] = s;
    __syncthreads();
    s = sredB[0];
    #pragma unroll
    for (int i = 1; i < 8; i++) s += sredB[i];

    e.x = e.x / s; e.y = e.y / s; e.z = e.z / s; e.w = e.w / s;
    ((float4*)p)[t] = e;

    float vmin = fminf(fminf(e.x, e.y), fminf(e.z, e.w));
    float vmax = fmaxf(fmaxf(e.x, e.y), fmaxf(e.z, e.w));
    block_minmax_commit(vmin, vmax, 4, t, 256);
}

// ctx[b,q,h,d] = sum_k fq(att)*vh.  Writes fq'd att back in place (final output),
// tensor-core GEMM. CTA = 128 rows x 64 (full D). grid (8, 128), block 256 (4x2 warps).
__global__ void __launch_bounds__(256) k_attgemm(float* __restrict__ att,
                                                 float* __restrict__ ctx) {
    __shared__ uint4 At[128 * 8];      // att tile as fp16 ints
    __shared__ uint4 Vt[64 * 8];

    int bh = blockIdx.y;
    int b = bh >> 4, h = bh & 15;
    int q0 = blockIdx.x * 128;
    int tid = threadIdx.x;
    int wid = tid >> 5, l = tid & 31;
    int wm = wid >> 1, wn = wid & 1;   // warp tile: 32 rows x 32 cols

    float s_a, zp_a, s_v, zp_v;
    get_sz(4, s_a, zp_a);
    get_sz(2, s_v, zp_v);

    float acc[2][4][4];
    #pragma unroll
    for (int i = 0; i < 2; i++)
        #pragma unroll
        for (int j = 0; j < 4; j++)
            #pragma unroll
            for (int e = 0; e < 4; e++) acc[i][j][e] = 0.0f;

    unsigned abase = smem_u32(At), vbase = smem_u32(Vt);

    for (int kk = 0; kk < 16; kk++) {
        // att tile: fq on load, write dequant back, fp16 ints into smem
        #pragma unroll
        for (int i = 0; i < 4; i++) {
            int g = tid + i * 256;
            int r = g >> 3, c8 = g & 7;
            float* ap = att + ((size_t)bh * W_ + q0 + r) * W_ + kk * 64 + c8 * 8;
            float4 fa = *(float4*)ap;
            float4 fb = *(float4*)(ap + 4);
            float i0 = fq_q(fa.x, s_a, zp_a), i1 = fq_q(fa.y, s_a, zp_a);
            float i2 = fq_q(fa.z, s_a, zp_a), i3 = fq_q(fa.w, s_a, zp_a);
            float i4 = fq_q(fb.x, s_a, zp_a), i5 = fq_q(fb.y, s_a, zp_a);
            float i6 = fq_q(fb.z, s_a, zp_a), i7 = fq_q(fb.w, s_a, zp_a);
            fa.x = i0 * s_a; fa.y = i1 * s_a; fa.z = i2 * s_a; fa.w = i3 * s_a;
            fb.x = i4 * s_a; fb.y = i5 * s_a; fb.z = i6 * s_a; fb.w = i7 * s_a;
            *(float4*)ap = fa;
            *(float4*)(ap + 4) = fb;
            union { __half2 h2; unsigned u; } p0, p1, p2, p3;
            p0.h2 = __floats2half2_rn(i0, i1); p1.h2 = __floats2half2_rn(i2, i3);
            p2.h2 = __floats2half2_rn(i4, i5); p3.h2 = __floats2half2_rn(i6, i7);
            At[r * 8 + (c8 ^ (r & 7))] = make_uint4(p0.u, p1.u, p2.u, p3.u);
        }
        // V tile: 64 rows x 64 halves
        const uint4* vsrc = (const uint4*)(g_vh + ((size_t)bh * W_ + kk * 64) * D_);
        #pragma unroll
        for (int i = 0; i < 2; i++) {
            int g = tid + i * 256;
            int r = g >> 3, c = g & 7;
            Vt[r * 8 + (c ^ (r & 7))] = vsrc[g];
        }
        __syncthreads();

        #pragma unroll
        for (int kc = 0; kc < 4; kc++) {
            unsigned a[2][4];
            #pragma unroll
            for (int mi = 0; mi < 2; mi++) {
                int row = wm * 32 + mi * 16 + (l & 15);
                int ch  = kc * 2 + (l >> 4);
                ldsm_x4(abase + (row * 8 + (ch ^ (row & 7))) * 16,
                        a[mi][0], a[mi][1], a[mi][2], a[mi][3]);
            }
            unsigned bf[4][2];
            int rv = kc * 16 + (l & 15);
            #pragma unroll
            for (int ni = 0; ni < 4; ni++) {
                int ch = wn * 4 + ni;
                ldsm_x2t(vbase + (rv * 8 + (ch ^ (rv & 7))) * 16, bf[ni][0], bf[ni][1]);
            }
            #pragma unroll
            for (int mi = 0; mi < 2; mi++)
                #pragma unroll
                for (int ni = 0; ni < 4; ni++)
                    mma16816(acc[mi][ni], a[mi][0], a[mi][1], a[mi][2], a[mi][3],
                             bf[ni][0], bf[ni][1]);
        }
        __syncthreads();
    }

    float sc = s_a * s_v;
    float vmin = FLT_BIG, vmax = -FLT_BIG;
    #pragma unroll
    for (int mi = 0; mi < 2; mi++) {
        int r0 = q0 + wm * 32 + mi * 16 + (l >> 2);
        #pragma unroll
        for (int ni = 0; ni < 4; ni++) {
            int d = wn * 32 + ni * 8 + (l & 3) * 2;
            float v0 = acc[mi][ni][0] * sc, v1 = acc[mi][ni][1] * sc;
            float v2 = acc[mi][ni][2] * sc, v3 = acc[mi][ni][3] * sc;
            vmin = fminf(vmin, fminf(fminf(v0, v1), fminf(v2, v3)));
            vmax = fmaxf(vmax, fmaxf(fmaxf(v0, v1), fmaxf(v2, v3)));
            size_t o0 = ((size_t)(b * W_ + r0) * H_ + h) * D_ + d;
            size_t o1 = ((size_t)(b * W_ + r0 + 8) * H_ + h) * D_ + d;
            *(float2*)(ctx + o0) = make_float2(v0, v1);
            *(float2*)(ctx + o1) = make_float2(v2, v3);
        }
    }
    block_minmax_commit(vmin, vmax, 5, tid, 256);
}

__global__ void __launch_bounds__(256) k_fqctx(float* __restrict__ ctx) {
    float s5, z5;
    get_sz(5, s5, z5);
    for (int i = blockIdx.x * blockDim.x + threadIdx.x; i < NQKV; i += gridDim.x * blockDim.x) {
        ctx[i] = fq_q(ctx[i], s5, z5) * s5;
    }
}

// ---------------- launch ----------------
extern "C" void kernel_launch(void* const* d_in, const int* in_sizes, int n_in,
                              void* d_out, int out_size) {
    const float* q = (const float*)d_in[0];
    const float* k = (const float*)d_in[1];
    const float* v = (const float*)d_in[2];

    float* ctx = (float*)d_out;
    float* att = (float*)d_out + ((size_t)out_size - NATT);

    k_init<<<1, 32>>>();

    k_minmax<<<512, 256>>>((const float4*)q, NQKV / 4, 0);
    k_minmax<<<512, 256>>>((const float4*)k, NQKV / 4, 1);
    k_minmax<<<512, 256>>>((const float4*)v, NQKV / 4, 2);

    k_quant<<<B_ * W_, 256>>>(q, k, v);

    dim3 gsc(8, 8, BH_);
    k_scores<<<gsc, 256>>>(att);

    k_softmax<<<BH_ * W_, 256>>>(att);

    dim3 gag(8, BH_);
    k_attgemm<<<gag, 256>>>(att, ctx);

    k_fqctx<<<2048, 256>>>(ctx);
}

// round 6
// speedup vs baseline: 2.9562x; 1.5279x over previous
#include <cuda_runtime.h>
#include <cuda_fp16.h>
#include <stdint.h>
#include <math.h>

#define B_   8
#define W_   1024
#define H_   16
#define D_   64
#define BH_  (B_ * H_)
#define NQKV (B_ * W_ * H_ * D_)        /* 8,388,608  */
#define NATT ((size_t)BH_ * W_ * W_)    /* 134,217,728 */

#define FLT_BIG 3.402823466e38f

// quantized (q_int - zp) values as fp16, layout [BH][W][D]
__device__ __half g_qh[NQKV];
__device__ __half g_kh[NQKV];
__device__ __half g_vh[NQKV];
// min/max accumulators (ordered-uint), slots: 0=q 1=k 2=v 3=scores 4=att 5=ctx
__device__ unsigned g_omin[6];
__device__ unsigned g_omax[6];

// ---------------- float <-> order-preserving uint ----------------
__device__ __forceinline__ unsigned f2o(float f) {
    unsigned u = __float_as_uint(f);
    return (u & 0x80000000u) ? ~u : (u | 0x80000000u);
}
__device__ __forceinline__ float o2f(unsigned u) {
    return (u & 0x80000000u) ? __uint_as_float(u & 0x7fffffffu)
                             : __uint_as_float(~u);
}

// ---------------- fake-quant helpers ----------------
__device__ __forceinline__ void get_sz(int slot, float& s, float& zp) {
    float mn = o2f(g_omin[slot]);
    float mx = o2f(g_omax[slot]);
    s  = fmaxf((mx - mn) / 255.0f, 1e-8f);
    zp = fminf(fmaxf(rintf(-128.0f - mn / s), -128.0f), 127.0f);
}
// returns (q_int - zp): integer-valued float in [-255,255]. dequant = ret * s
__device__ __forceinline__ float fq_q(float x, float inv_s, float zp) {
    return fminf(fmaxf(rintf(x * inv_s) + zp, -128.0f), 127.0f) - zp;
}

// ---------------- min/max commits ----------------
// block-level (uses 64B smem) — NOT for k_attgemm (smem budget exact there)
__device__ __forceinline__ void block_minmax_commit(float vmin, float vmax, int slot,
                                                    int tid, int nthreads) {
    #pragma unroll
    for (int o = 16; o; o >>= 1) {
        vmin = fminf(vmin, __shfl_xor_sync(0xffffffffu, vmin, o));
        vmax = fmaxf(vmax, __shfl_xor_sync(0xffffffffu, vmax, o));
    }
    __shared__ float smn[8], smx[8];
    int w = tid >> 5, l = tid & 31;
    int nw = (nthreads + 31) >> 5;
    if (l == 0) { smn[w] = vmin; smx[w] = vmax; }
    __syncthreads();
    if (w == 0) {
        vmin = (l < nw) ? smn[l] : FLT_BIG;
        vmax = (l < nw) ? smx[l] : -FLT_BIG;
        #pragma unroll
        for (int o = 4; o; o >>= 1) {
            vmin = fminf(vmin, __shfl_xor_sync(0xffffffffu, vmin, o));
            vmax = fmaxf(vmax, __shfl_xor_sync(0xffffffffu, vmax, o));
        }
        if (l == 0) {
            atomicMin(&g_omin[slot], f2o(vmin));
            atomicMax(&g_omax[slot], f2o(vmax));
        }
    }
    __syncthreads();
}

// warp-level (no smem): each warp's lane 0 commits directly
__device__ __forceinline__ void warp_minmax_commit(float vmin, float vmax, int slot, int lane) {
    #pragma unroll
    for (int o = 16; o; o >>= 1) {
        vmin = fminf(vmin, __shfl_xor_sync(0xffffffffu, vmin, o));
        vmax = fmaxf(vmax, __shfl_xor_sync(0xffffffffu, vmax, o));
    }
    if (lane == 0) {
        atomicMin(&g_omin[slot], f2o(vmin));
        atomicMax(&g_omax[slot], f2o(vmax));
    }
}

// ---------------- ldmatrix / mma / cp.async wrappers ----------------
__device__ __forceinline__ unsigned smem_u32(const void* p) {
    return (unsigned)__cvta_generic_to_shared(p);
}
__device__ __forceinline__ void ldsm_x4(unsigned a, unsigned& r0, unsigned& r1,
                                        unsigned& r2, unsigned& r3) {
    asm volatile("ldmatrix.sync.aligned.m8n8.x4.shared.b16 {%0,%1,%2,%3}, [%4];"
                 : "=r"(r0), "=r"(r1), "=r"(r2), "=r"(r3) : "r"(a));
}
__device__ __forceinline__ void ldsm_x2(unsigned a, unsigned& r0, unsigned& r1) {
    asm volatile("ldmatrix.sync.aligned.m8n8.x2.shared.b16 {%0,%1}, [%2];"
                 : "=r"(r0), "=r"(r1) : "r"(a));
}
__device__ __forceinline__ void ldsm_x2t(unsigned a, unsigned& r0, unsigned& r1) {
    asm volatile("ldmatrix.sync.aligned.m8n8.x2.trans.shared.b16 {%0,%1}, [%2];"
                 : "=r"(r0), "=r"(r1) : "r"(a));
}
__device__ __forceinline__ void mma16816(float* d, unsigned a0, unsigned a1,
                                         unsigned a2, unsigned a3,
                                         unsigned b0, unsigned b1) {
    asm volatile(
        "mma.sync.aligned.m16n8k16.row.col.f32.f16.f16.f32 "
        "{%0,%1,%2,%3}, {%4,%5,%6,%7}, {%8,%9}, {%0,%1,%2,%3};"
        : "+f"(d[0]), "+f"(d[1]), "+f"(d[2]), "+f"(d[3])
        : "r"(a0), "r"(a1), "r"(a2), "r"(a3), "r"(b0), "r"(b1));
}
__device__ __forceinline__ void cp_async16(unsigned dst, const void* src) {
    asm volatile("cp.async.cg.shared.global [%0], [%1], 16;"
                 :: "r"(dst), "l"(src));
}
__device__ __forceinline__ void cp_async_commit() {
    asm volatile("cp.async.commit_group;");
}
__device__ __forceinline__ void cp_async_wait0() {
    asm volatile("cp.async.wait_group 0;");
}

// ---------------- kernels ----------------
__global__ void k_init() {
    int i = threadIdx.x;
    if (i < 6) { g_omin[i] = 0xFFFFFFFFu; g_omax[i] = 0u; }
}

// one launch, three tensors: slot = blockIdx.x / 512
__global__ void __launch_bounds__(256) k_minmax3(const float4* __restrict__ q,
                                                 const float4* __restrict__ k,
                                                 const float4* __restrict__ v) {
    int slot = blockIdx.x >> 9;
    const float4* x = (slot == 0) ? q : (slot == 1) ? k : v;
    int n4 = NQKV / 4;
    float vmin = FLT_BIG, vmax = -FLT_BIG;
    for (int i = (blockIdx.x & 511) * 256 + threadIdx.x; i < n4; i += 512 * 256) {
        float4 f = x[i];
        vmin = fminf(vmin, fminf(fminf(f.x, f.y), fminf(f.z, f.w)));
        vmax = fmaxf(vmax, fmaxf(fmaxf(f.x, f.y), fmaxf(f.z, f.w)));
    }
    block_minmax_commit(vmin, vmax, slot, threadIdx.x, 256);
}

// quantize q/k/v into fp16 (q_int - zp) values, transposed to [BH][W][D].
__global__ void __launch_bounds__(256) k_quant(const float* __restrict__ q,
                                               const float* __restrict__ k,
                                               const float* __restrict__ v) {
    float s0, z0, s1, z1, s2, z2;
    get_sz(0, s0, z0); get_sz(1, s1, z1); get_sz(2, s2, z2);
    float i0 = 1.0f / s0, i1 = 1.0f / s1, i2 = 1.0f / s2;

    int bw = blockIdx.x;               // b*W + w
    int b = bw >> 10, w = bw & 1023;
    int t = threadIdx.x;
    int h = t >> 4, d4 = (t & 15) * 4;

    size_t src = ((size_t)bw * H_ + h) * D_ + d4;
    size_t dst = (((size_t)(b * H_ + h)) * W_ + w) * D_ + d4;

    union { __half2 h2; unsigned u; } p0, p1;

    float4 fv = *(const float4*)(q + src);
    p0.h2 = __floats2half2_rn(fq_q(fv.x, i0, z0), fq_q(fv.y, i0, z0));
    p1.h2 = __floats2half2_rn(fq_q(fv.z, i0, z0), fq_q(fv.w, i0, z0));
    *(uint2*)(g_qh + dst) = make_uint2(p0.u, p1.u);

    fv = *(const float4*)(k + src);
    p0.h2 = __floats2half2_rn(fq_q(fv.x, i1, z1), fq_q(fv.y, i1, z1));
    p1.h2 = __floats2half2_rn(fq_q(fv.z, i1, z1), fq_q(fv.w, i1, z1));
    *(uint2*)(g_kh + dst) = make_uint2(p0.u, p1.u);

    fv = *(const float4*)(v + src);
    p0.h2 = __floats2half2_rn(fq_q(fv.x, i2, z2), fq_q(fv.y, i2, z2));
    p1.h2 = __floats2half2_rn(fq_q(fv.z, i2, z2), fq_q(fv.w, i2, z2));
    *(uint2*)(g_vh + dst) = make_uint2(p0.u, p1.u);
}

// scores[bh,qi,ki] = (sum_d qh*kh) * s_q*s_k/8.  CTA = 128x128 tile, K=64.
// grid (8, 8, 128), block 256 (8 warps as 2x4). HMMA.
__global__ void __launch_bounds__(256) k_scores(float* __restrict__ scores) {
    __shared__ uint4 At[128 * 8];
    __shared__ uint4 Kt[128 * 8];

    int bh = blockIdx.z;
    int q0 = blockIdx.y * 128, k0 = blockIdx.x * 128;
    int tid = threadIdx.x;

    const uint4* qsrc = (const uint4*)(g_qh + ((size_t)bh * W_ + q0) * D_);
    const uint4* ksrc = (const uint4*)(g_kh + ((size_t)bh * W_ + k0) * D_);
    #pragma unroll
    for (int i = 0; i < 4; i++) {
        int g = tid + i * 256;
        int r = g >> 3, c = g & 7;
        At[r * 8 + (c ^ (r & 7))] = qsrc[g];
        Kt[r * 8 + (c ^ (r & 7))] = ksrc[g];
    }
    __syncthreads();

    int wid = tid >> 5, l = tid & 31;
    int wm = wid >> 2, wn = wid & 3;   // warp tile: 64 rows x 32 cols

    float acc[4][4][4];
    #pragma unroll
    for (int i = 0; i < 4; i++)
        #pragma unroll
        for (int j = 0; j < 4; j++)
            #pragma unroll
            for (int e = 0; e < 4; e++) acc[i][j][e] = 0.0f;

    unsigned abase = smem_u32(At), kbase = smem_u32(Kt);

    #pragma unroll
    for (int kc = 0; kc < 4; kc++) {
        unsigned a[4][4];
        #pragma unroll
        for (int mi = 0; mi < 4; mi++) {
            int row = wm * 64 + mi * 16 + (l & 15);
            int ch  = kc * 2 + (l >> 4);
            ldsm_x4(abase + (row * 8 + (ch ^ (row & 7))) * 16,
                    a[mi][0], a[mi][1], a[mi][2], a[mi][3]);
        }
        unsigned bf[4][2];
        #pragma unroll
        for (int ni = 0; ni < 4; ni++) {
            int row = wn * 32 + ni * 8 + (l & 7);
            int ch  = kc * 2 + ((l >> 3) & 1);
            ldsm_x2(kbase + (row * 8 + (ch ^ (row & 7))) * 16, bf[ni][0], bf[ni][1]);
        }
        #pragma unroll
        for (int mi = 0; mi < 4; mi++)
            #pragma unroll
            for (int ni = 0; ni < 4; ni++)
                mma16816(acc[mi][ni], a[mi][0], a[mi][1], a[mi][2], a[mi][3],
                         bf[ni][0], bf[ni][1]);
    }

    float s0, z0, s1, z1;
    get_sz(0, s0, z0); get_sz(1, s1, z1);
    float sc = s0 * s1 * 0.125f;

    float vmin = FLT_BIG, vmax = -FLT_BIG;
    #pragma unroll
    for (int mi = 0; mi < 4; mi++) {
        int r0 = q0 + wm * 64 + mi * 16 + (l >> 2);
        #pragma unroll
        for (int ni = 0; ni < 4; ni++) {
            int c = k0 + wn * 32 + ni * 8 + (l & 3) * 2;
            float v0 = acc[mi][ni][0] * sc, v1 = acc[mi][ni][1] * sc;
            float v2 = acc[mi][ni][2] * sc, v3 = acc[mi][ni][3] * sc;
            vmin = fminf(vmin, fminf(fminf(v0, v1), fminf(v2, v3)));
            vmax = fmaxf(vmax, fmaxf(fmaxf(v0, v1), fmaxf(v2, v3)));
            size_t base = ((size_t)bh * W_ + r0) * W_ + c;
            *(float2*)(scores + base)           = make_float2(v0, v1);
            *(float2*)(scores + base + 8 * W_)  = make_float2(v2, v3);
        }
    }
    block_minmax_commit(vmin, vmax, 3, tid, 256);
}

// warp-per-row softmax: 8 rows per 256-thread block.
// fq(scores,3) -> softmax -> write att (pre-fq) -> minmax slot4
__global__ void __launch_bounds__(256) k_softmax(float* __restrict__ att) {
    int wid = threadIdx.x >> 5, l = threadIdx.x & 31;
    size_t row = (size_t)blockIdx.x * 8 + wid;
    float4* p4 = (float4*)(att + row * W_);

    float s3, z3;
    get_sz(3, s3, z3);
    float inv3 = 1.0f / s3;

    float4 v[8];
    #pragma unroll
    for (int i = 0; i < 8; i++) v[i] = p4[l + 32 * i];

    float m = -FLT_BIG;
    #pragma unroll
    for (int i = 0; i < 8; i++) {
        v[i].x = fq_q(v[i].x, inv3, z3) * s3;
        v[i].y = fq_q(v[i].y, inv3, z3) * s3;
        v[i].z = fq_q(v[i].z, inv3, z3) * s3;
        v[i].w = fq_q(v[i].w, inv3, z3) * s3;
        m = fmaxf(m, fmaxf(fmaxf(v[i].x, v[i].y), fmaxf(v[i].z, v[i].w)));
    }
    #pragma unroll
    for (int o = 16; o; o >>= 1) m = fmaxf(m, __shfl_xor_sync(0xffffffffu, m, o));

    float s = 0.0f;
    #pragma unroll
    for (int i = 0; i < 8; i++) {
        v[i].x = __expf(v[i].x - m); v[i].y = __expf(v[i].y - m);
        v[i].z = __expf(v[i].z - m); v[i].w = __expf(v[i].w - m);
        s += (v[i].x + v[i].y) + (v[i].z + v[i].w);
    }
    #pragma unroll
    for (int o = 16; o; o >>= 1) s += __shfl_xor_sync(0xffffffffu, s, o);
    float inv_sum = 1.0f / s;

    float vmin = FLT_BIG, vmax = -FLT_BIG;
    #pragma unroll
    for (int i = 0; i < 8; i++) {
        v[i].x *= inv_sum; v[i].y *= inv_sum;
        v[i].z *= inv_sum; v[i].w *= inv_sum;
        p4[l + 32 * i] = v[i];
        vmin = fminf(vmin, fminf(fminf(v[i].x, v[i].y), fminf(v[i].z, v[i].w)));
        vmax = fmaxf(vmax, fmaxf(fmaxf(v[i].x, v[i].y), fmaxf(v[i].z, v[i].w)));
    }
    warp_minmax_commit(vmin, vmax, 4, l);
}

// ctx = fq(att)*vh, double-buffered pipeline. Writes fq'd att back (final output).
// grid (8, 128), block 256 (warps 4x2). CTA tile: 128 q-rows x 64 D, K-chunks of 64.
// smem: At 32KB + Vt 16KB = 49152 = exactly the static limit -> minmax via warp commits.
__global__ void __launch_bounds__(256) k_attgemm(float* __restrict__ att,
                                                 float* __restrict__ ctx) {
    __shared__ uint4 At[2][128 * 8];
    __shared__ uint4 Vt[2][64 * 8];

    int bh = blockIdx.y;
    int b = bh >> 4, h = bh & 15;
    int q0 = blockIdx.x * 128;
    int tid = threadIdx.x;
    int wid = tid >> 5, l = tid & 31;
    int wm = wid >> 1, wn = wid & 1;   // warp tile: 32 rows x 32 cols

    float s_a, zp_a, s_v, zp_v;
    get_sz(4, s_a, zp_a);
    get_sz(2, s_v, zp_v);
    float inv_a = 1.0f / s_a;

    float acc[2][4][4];
    #pragma unroll
    for (int i = 0; i < 2; i++)
        #pragma unroll
        for (int j = 0; j < 4; j++)
            #pragma unroll
            for (int e = 0; e < 4; e++) acc[i][j][e] = 0.0f;

    // per-thread att addresses: 4 groups, each 8 consecutive floats
    int gr[4], gc[4];
    #pragma unroll
    for (int i = 0; i < 4; i++) {
        int g = tid + i * 256;
        gr[i] = g >> 3;            // row 0..127
        gc[i] = g & 7;             // chunk of 8 floats
    }
    const uint4* vsrc_base = (const uint4*)(g_vh + (size_t)bh * W_ * D_);

    float4 pre[8];

    auto load_att = [&](int kk) {
        #pragma unroll
        for (int i = 0; i < 4; i++) {
            const float* ap = att + ((size_t)bh * W_ + q0 + gr[i]) * W_ + kk * 64 + gc[i] * 8;
            pre[i * 2]     = *(const float4*)ap;
            pre[i * 2 + 1] = *(const float4*)(ap + 4);
        }
    };
    auto fq_store = [&](int kk, int buf) {
        #pragma unroll
        for (int i = 0; i < 4; i++) {
            float* ap = att + ((size_t)bh * W_ + q0 + gr[i]) * W_ + kk * 64 + gc[i] * 8;
            float4 fa = pre[i * 2], fb = pre[i * 2 + 1];
            float j0 = fq_q(fa.x, inv_a, zp_a), j1 = fq_q(fa.y, inv_a, zp_a);
            float j2 = fq_q(fa.z, inv_a, zp_a), j3 = fq_q(fa.w, inv_a, zp_a);
            float j4 = fq_q(fb.x, inv_a, zp_a), j5 = fq_q(fb.y, inv_a, zp_a);
            float j6 = fq_q(fb.z, inv_a, zp_a), j7 = fq_q(fb.w, inv_a, zp_a);
            fa.x = j0 * s_a; fa.y = j1 * s_a; fa.z = j2 * s_a; fa.w = j3 * s_a;
            fb.x = j4 * s_a; fb.y = j5 * s_a; fb.z = j6 * s_a; fb.w = j7 * s_a;
            *(float4*)ap = fa;
            *(float4*)(ap + 4) = fb;
            union { __half2 h2; unsigned u; } p0, p1, p2, p3;
            p0.h2 = __floats2half2_rn(j0, j1); p1.h2 = __floats2half2_rn(j2, j3);
            p2.h2 = __floats2half2_rn(j4, j5); p3.h2 = __floats2half2_rn(j6, j7);
            At[buf][gr[i] * 8 + (gc[i] ^ (gr[i] & 7))] = make_uint4(p0.u, p1.u, p2.u, p3.u);
        }
    };
    auto load_v = [&](int kk, int buf) {
        unsigned vb = smem_u32(Vt[buf]);
        #pragma unroll
        for (int i = 0; i < 2; i++) {
            int g = tid + i * 256;
            int r = g >> 3, c = g & 7;
            cp_async16(vb + (r * 8 + (c ^ (r & 7))) * 16,
                       vsrc_base + (size_t)kk * 64 * 8 + g);
        }
        cp_async_commit();
    };

    // prologue
    load_att(0);
    load_v(0, 0);
    fq_store(0, 0);
    cp_async_wait0();
    __syncthreads();

    for (int kk = 0; kk < 16; kk++) {
        int cur = kk & 1, nxt = cur ^ 1;
        if (kk < 15) {
            load_att(kk + 1);          // LDGs in flight during mma
            load_v(kk + 1, nxt);
        }

        unsigned abase = smem_u32(At[cur]), vbase = smem_u32(Vt[cur]);
        #pragma unroll
        for (int kc = 0; kc < 4; kc++) {
            unsigned a[2][4];
            #pragma unroll
            for (int mi = 0; mi < 2; mi++) {
                int row = wm * 32 + mi * 16 + (l & 15);
                int ch  = kc * 2 + (l >> 4);
                ldsm_x4(abase + (row * 8 + (ch ^ (row & 7))) * 16,
                        a[mi][0], a[mi][1], a[mi][2], a[mi][3]);
            }
            unsigned bf[4][2];
            int rv = kc * 16 + (l & 15);
            #pragma unroll
            for (int ni = 0; ni < 4; ni++) {
                int ch = wn * 4 + ni;
                ldsm_x2t(vbase + (rv * 8 + (ch ^ (rv & 7))) * 16, bf[ni][0], bf[ni][1]);
            }
            #pragma unroll
            for (int mi = 0; mi < 2; mi++)
                #pragma unroll
                for (int ni = 0; ni < 4; ni++)
                    mma16816(acc[mi][ni], a[mi][0], a[mi][1], a[mi][2], a[mi][3],
                             bf[ni][0], bf[ni][1]);
        }

        if (kk < 15) {
            fq_store(kk + 1, nxt);
            cp_async_wait0();
        }
        __syncthreads();
    }

    float sc = s_a * s_v;
    float vmin = FLT_BIG, vmax = -FLT_BIG;
    #pragma unroll
    for (int mi = 0; mi < 2; mi++) {
        int r0 = q0 + wm * 32 + mi * 16 + (l >> 2);
        #pragma unroll
        for (int ni = 0; ni < 4; ni++) {
            int d = wn * 32 + ni * 8 + (l & 3) * 2;
            float v0 = acc[mi][ni][0] * sc, v1 = acc[mi][ni][1] * sc;
            float v2 = acc[mi][ni][2] * sc, v3 = acc[mi][ni][3] * sc;
            vmin = fminf(vmin, fminf(fminf(v0, v1), fminf(v2, v3)));
            vmax = fmaxf(vmax, fmaxf(fmaxf(v0, v1), fmaxf(v2, v3)));
            size_t o0 = ((size_t)(b * W_ + r0) * H_ + h) * D_ + d;
            size_t o1 = ((size_t)(b * W_ + r0 + 8) * H_ + h) * D_ + d;
            *(float2*)(ctx + o0) = make_float2(v0, v1);
            *(float2*)(ctx + o1) = make_float2(v2, v3);
        }
    }
    warp_minmax_commit(vmin, vmax, 5, l);
}

__global__ void __launch_bounds__(256) k_fqctx(float* __restrict__ ctx) {
    float s5, z5;
    get_sz(5, s5, z5);
    float inv5 = 1.0f / s5;
    for (int i = blockIdx.x * blockDim.x + threadIdx.x; i < NQKV; i += gridDim.x * blockDim.x) {
        ctx[i] = fq_q(ctx[i], inv5, z5) * s5;
    }
}

// ---------------- launch ----------------
extern "C" void kernel_launch(void* const* d_in, const int* in_sizes, int n_in,
                              void* d_out, int out_size) {
    const float* q = (const float*)d_in[0];
    const float* k = (const float*)d_in[1];
    const float* v = (const float*)d_in[2];

    float* ctx = (float*)d_out;
    float* att = (float*)d_out + ((size_t)out_size - NATT);

    k_init<<<1, 32>>>();

    k_minmax3<<<1536, 256>>>((const float4*)q, (const float4*)k, (const float4*)v);

    k_quant<<<B_ * W_, 256>>>(q, k, v);

    dim3 gsc(8, 8, BH_);
    k_scores<<<gsc, 256>>>(att);

    k_softmax<<<BH_ * W_ / 8, 256>>>(att);

    dim3 gag(8, BH_);
    k_attgemm<<<gag, 256>>>(att, ctx);

    k_fqctx<<<2048, 256>>>(ctx);
}